// round 16
// baseline (speedup 1.0000x reference)
#include <cuda_runtime.h>
#include <cuda_bf16.h>
#include <cstdint>

#define B_ 128
#define T_ 4096
#define F_ 64
#define H_ 128
#define G_ 512   /* 4*H */

// Scratch: precomputed input gates, PERMUTED + PAIRED layout, 1 GiB.
// lstm thread t (r=t>>1) reads ONE float2 at slot pair (2t, 2t+1):
//   slot 2t   = xg of rowA(t)   (even t: i_r, odd t: g_r)
//   slot 2t+1 = xg of rowB(t)   (even t: f_r, odd t: o_r)
__device__ float g_xg[268435456ull];

// ---------------- f32x2 helpers (packed fp32: 2x FFMA throughput) ----------
__device__ __forceinline__ unsigned long long packf2(float x, float y) {
    unsigned long long r;
    asm("mov.b64 %0, {%1, %2};" : "=l"(r) : "f"(x), "f"(y));
    return r;
}
__device__ __forceinline__ float2 unpackf2(unsigned long long v) {
    float2 r;
    asm("mov.b64 {%0, %1}, %2;" : "=f"(r.x), "=f"(r.y) : "l"(v));
    return r;
}
__device__ __forceinline__ unsigned long long ffma2(unsigned long long a,
                                                    unsigned long long b,
                                                    unsigned long long c) {
    unsigned long long d;
    asm("fma.rn.f32x2 %0, %1, %2, %3;" : "=l"(d) : "l"(a), "l"(b), "l"(c));
    return d;
}
// bf16x2 (u32, low=first) -> f32x2 (u64). Pure ALU-pipe ops.
__device__ __forceinline__ unsigned long long bf2tof2(unsigned int u) {
    unsigned int lo = u << 16;
    unsigned int hi = u & 0xFFFF0000u;
    unsigned long long r;
    asm("mov.b64 %0, {%1, %2};" : "=l"(r) : "r"(lo), "r"(hi));
    return r;
}
__device__ __forceinline__ unsigned int packbf(float x, float y) {
    unsigned short sx = __bfloat16_as_ushort(__float2bfloat16(x));
    unsigned short sy = __bfloat16_as_ushort(__float2bfloat16(y));
    return ((unsigned)sy << 16) | (unsigned)sx;
}

// ACCURATE activations (proven 2.9e-7; approx diverges over T=4096).
__device__ __forceinline__ float sigmoidf_(float x) {
    return __fdividef(1.0f, 1.0f + __expf(-x));
}
__device__ __forceinline__ float tanhf_(float x) {
    float ax = fabsf(x);
    float e  = __expf(-2.0f * ax);
    float t  = __fdividef(1.0f - e, 1.0f + e);
    return copysignf(t, x);
}

// original gate row for slot pair of thread t: even->i_r, odd->g_r (B=+128)
__device__ __host__ __forceinline__ int perm_rowA(int t) {
    int r = t >> 1;
    return (t & 1) ? (256 + r) : r;
}

// ---------------------------------------------------------------------------
// Kernel 1: xg precompute, paired-permuted output. grid (T/64, B), 256 thr.
// ---------------------------------------------------------------------------
__global__ __launch_bounds__(256) void xg_kernel(
    const float* __restrict__ X,
    const float* __restrict__ W_ih,
    const float* __restrict__ b_ih,
    const float* __restrict__ b_hh)
{
    extern __shared__ float smem[];
    float* sW = smem;                 // 512 x 65 (pad 1 -> conflict-free)
    float* sX = smem + 512 * 65;      // 64 x 64

    const int t  = threadIdx.x;
    const int b  = blockIdx.y;
    const int t0 = blockIdx.x * 64;

    for (int idx = t; idx < 512 * 64; idx += 256) {
        int j = idx >> 6, k = idx & 63;
        sW[j * 65 + k] = W_ih[idx];
    }
    const float* Xb = X + ((size_t)b * T_ + t0) * F_;
    for (int idx = t; idx < 64 * 64; idx += 256) sX[idx] = Xb[idx];
    __syncthreads();

    const int jA = perm_rowA(t);
    const int jB = jA + 128;

    unsigned long long wpA[32], wpB[32];
#pragma unroll
    for (int p = 0; p < 32; ++p) {
        wpA[p] = packf2(sW[jA * 65 + 2 * p], sW[jA * 65 + 2 * p + 1]);
        wpB[p] = packf2(sW[jB * 65 + 2 * p], sW[jB * 65 + 2 * p + 1]);
    }
    const float biasA = __ldg(b_ih + jA) + __ldg(b_hh + jA);
    const float biasB = __ldg(b_ih + jB) + __ldg(b_hh + jB);

    float2* outb = (float2*)(g_xg + ((size_t)b * T_ + t0) * G_) + t;

    for (int tt = 0; tt < 64; ++tt) {
        const ulonglong2* x2 = (const ulonglong2*)(sX + tt * 64);
        unsigned long long aA0 = 0, aA1 = 0, aB0 = 0, aB1 = 0;
#pragma unroll
        for (int q = 0; q < 16; ++q) {
            ulonglong2 hq = x2[q];            // broadcast LDS.128
            aA0 = ffma2(wpA[2 * q],     hq.x, aA0);
            aA1 = ffma2(wpA[2 * q + 1], hq.y, aA1);
            aB0 = ffma2(wpB[2 * q],     hq.x, aB0);
            aB1 = ffma2(wpB[2 * q + 1], hq.y, aB1);
        }
        float2 u0 = unpackf2(aA0), u1 = unpackf2(aA1);
        float2 v0 = unpackf2(aB0), v1 = unpackf2(aB1);
        float2 o;
        o.x = (u0.x + u0.y) + (u1.x + u1.y) + biasA;
        o.y = (v0.x + v0.y) + (v1.x + v1.y) + biasB;
        outb[(size_t)tt * 256] = o;           // STG.64, coalesced
    }
}

// ---------------------------------------------------------------------------
// Kernel 2: persistent LSTM, TWO batch rows per CTA (grid = 64).
// 256 threads; thread t owns gate rows (rowA, rowB) for BOTH batch rows:
//   even t: (i_r, f_r), owns c_r of both rows
//   odd  t: (g_r, o_r), owns h_r of both rows
// Rationale: every per-step fixed cost (barrier, epilogue chain, load
// latency exposure) is paid ONCE for TWO rows; weights (batch-invariant)
// are shared; 8 independent FMA chains/thread -> deep ILP.
// Weights: k=0..79 resident fp32 (40 pairs x 2 gate rows = 160 regs,
// leaves headroom at the 255 cap); k=80..127 streamed bf16 from shared
// (12 uint4/thread/step, reused by both batch rows).
// One __syncthreads/step; shfl_xor epilogue; h double-buffered per row.
// ---------------------------------------------------------------------------
__global__ __launch_bounds__(256, 1) void lstm_kernel(
    const float* __restrict__ W_hh,
    float* __restrict__ out)
{
    __shared__ alignas(16) float sh_h[2][2][128];   // [row][buf][r], 2 KB
    extern __shared__ uint4 dsw[];                  // [12][256], 48 KB bf16 W

    const int t = threadIdx.x;
    const int b0 = blockIdx.x * 2;                  // batch rows b0, b0+1
    const int r = t >> 1;
    const bool odd = (t & 1) != 0;
    const int rowA = perm_rowA(t);                  // i_r or g_r
    const int rowB = rowA + 128;                    // f_r or o_r

    const float* WA = W_hh + (size_t)rowA * H_;
    const float* WB = W_hh + (size_t)rowB * H_;

    // k = 0..79 resident: 40 f32x2 pairs per gate row (160 regs)
    unsigned long long wpA[40], wpB[40];
#pragma unroll
    for (int q = 0; q < 20; ++q) {
        float4 a = __ldg((const float4*)(WA + 4 * q));
        wpA[2 * q]     = packf2(a.x, a.y);
        wpA[2 * q + 1] = packf2(a.z, a.w);
        float4 c4 = __ldg((const float4*)(WB + 4 * q));
        wpB[2 * q]     = packf2(c4.x, c4.y);
        wpB[2 * q + 1] = packf2(c4.z, c4.w);
    }
    // k = 80..127 as packed bf16: 6 uint4 per gate row, lane-major.
    // dsw[v]   = rowA chunk v,  dsw[6+v] = rowB chunk v   (v = 0..5)
#pragma unroll
    for (int v = 0; v < 6; ++v) {
        float4 a0 = __ldg((const float4*)(WA + 80 + 8 * v));
        float4 a1 = __ldg((const float4*)(WA + 84 + 8 * v));
        dsw[v * 256 + t] = make_uint4(packbf(a0.x, a0.y), packbf(a0.z, a0.w),
                                      packbf(a1.x, a1.y), packbf(a1.z, a1.w));
        float4 b0v = __ldg((const float4*)(WB + 80 + 8 * v));
        float4 b1v = __ldg((const float4*)(WB + 84 + 8 * v));
        dsw[(6 + v) * 256 + t] =
            make_uint4(packbf(b0v.x, b0v.y), packbf(b0v.z, b0v.w),
                       packbf(b1v.x, b1v.y), packbf(b1v.z, b1v.w));
    }
    // zero all four h buffers (2 rows x 2 bufs x 128 = 512 floats)
    ((float*)sh_h)[t] = 0.0f;
    ((float*)sh_h)[t + 256] = 0.0f;
    __syncthreads();

    const float2* pf0 = (const float2*)(g_xg + (size_t)(b0 + 0) * T_ * G_) + t;
    const float2* pf1 = (const float2*)(g_xg + (size_t)(b0 + 1) * T_ * G_) + t;
    float2 xg0 = __ldg(pf0);                        // step 0's xg, both rows
    float2 xg1 = __ldg(pf1);

    float c0 = 0.0f, c1 = 0.0f;
    float ho0 = 0.0f, ho1 = 0.0f;

    for (int ts = 0; ts < T_; ++ts) {
        const int inc = (ts < T_ - 1) ? 256 : 0;    // clamped on last step
        float2 nx0 = __ldg(pf0 + inc);              // next-step prefetch
        float2 nx1 = __ldg(pf1 + inc);

        const ulonglong2* h0v = (const ulonglong2*)sh_h[0][ts & 1];
        const ulonglong2* h1v = (const ulonglong2*)sh_h[1][ts & 1];

        unsigned long long a0A0 = 0, a0A1 = 0, a0B0 = 0, a0B1 = 0;  // row 0
        unsigned long long a1A0 = 0, a1A1 = 0, a1B0 = 0, a1B1 = 0;  // row 1
#pragma unroll
        for (int q = 0; q < 20; ++q) {              // k=0..79, resident W
            ulonglong2 h0 = h0v[q];                 // broadcast LDS.128
            ulonglong2 h1 = h1v[q];
            a0A0 = ffma2(wpA[2 * q],     h0.x, a0A0);
            a0A1 = ffma2(wpA[2 * q + 1], h0.y, a0A1);
            a0B0 = ffma2(wpB[2 * q],     h0.x, a0B0);
            a0B1 = ffma2(wpB[2 * q + 1], h0.y, a0B1);
            a1A0 = ffma2(wpA[2 * q],     h1.x, a1A0);
            a1A1 = ffma2(wpA[2 * q + 1], h1.y, a1A1);
            a1B0 = ffma2(wpB[2 * q],     h1.x, a1B0);
            a1B1 = ffma2(wpB[2 * q + 1], h1.y, a1B1);
        }
#pragma unroll
        for (int v = 0; v < 6; ++v) {               // k=80..127, streamed bf16
            uint4 ua = dsw[v * 256 + t];
            uint4 ub = dsw[(6 + v) * 256 + t];
            unsigned long long wa0 = bf2tof2(ua.x), wa1 = bf2tof2(ua.y);
            unsigned long long wa2 = bf2tof2(ua.z), wa3 = bf2tof2(ua.w);
            unsigned long long wb0 = bf2tof2(ub.x), wb1 = bf2tof2(ub.y);
            unsigned long long wb2 = bf2tof2(ub.z), wb3 = bf2tof2(ub.w);
            ulonglong2 p0 = h0v[20 + 2 * v];
            ulonglong2 p1 = h0v[21 + 2 * v];
            a0A0 = ffma2(wa0, p0.x, a0A0);
            a0A1 = ffma2(wa1, p0.y, a0A1);
            a0A0 = ffma2(wa2, p1.x, a0A0);
            a0A1 = ffma2(wa3, p1.y, a0A1);
            a0B0 = ffma2(wb0, p0.x, a0B0);
            a0B1 = ffma2(wb1, p0.y, a0B1);
            a0B0 = ffma2(wb2, p1.x, a0B0);
            a0B1 = ffma2(wb3, p1.y, a0B1);
            ulonglong2 q0 = h1v[20 + 2 * v];
            ulonglong2 q1 = h1v[21 + 2 * v];
            a1A0 = ffma2(wa0, q0.x, a1A0);
            a1A1 = ffma2(wa1, q0.y, a1A1);
            a1A0 = ffma2(wa2, q1.x, a1A0);
            a1A1 = ffma2(wa3, q1.y, a1A1);
            a1B0 = ffma2(wb0, q0.x, a1B0);
            a1B1 = ffma2(wb1, q0.y, a1B1);
            a1B0 = ffma2(wb2, q1.x, a1B0);
            a1B1 = ffma2(wb3, q1.y, a1B1);
        }

        // ---- epilogue, batch row 0 ----
        float2 u0 = unpackf2(a0A0), u1 = unpackf2(a0A1);
        float2 w0 = unpackf2(a0B0), w1 = unpackf2(a0B1);
        float gA0 = (u0.x + u0.y) + (u1.x + u1.y) + xg0.x;
        float gB0 = (w0.x + w0.y) + (w1.x + w1.y) + xg0.y;
        // ---- epilogue, batch row 1 ----
        float2 s0 = unpackf2(a1A0), s1 = unpackf2(a1A1);
        float2 z0 = unpackf2(a1B0), z1 = unpackf2(a1B1);
        float gA1 = (s0.x + s0.y) + (s1.x + s1.y) + xg1.x;
        float gB1 = (z0.x + z0.y) + (z1.x + z1.y) + xg1.y;

        // even: a=sig(i), bb=sig(f)   odd: a=tanh(g), bb=sig(o)
        float a0 = odd ? tanhf_(gA0) : sigmoidf_(gA0);
        float b0a = sigmoidf_(gB0);
        float a1 = odd ? tanhf_(gA1) : sigmoidf_(gA1);
        float b1a = sigmoidf_(gB1);

        float aX0 = __shfl_xor_sync(0xFFFFFFFFu, a0, 1);
        float aX1 = __shfl_xor_sync(0xFFFFFFFFu, a1, 1);
        float tc0 = 0.0f, tc1 = 0.0f;
        if (!odd) {
            c0 = fmaf(b0a, c0, a0 * aX0);            // c = f*c + i*g
            c1 = fmaf(b1a, c1, a1 * aX1);
            tc0 = tanhf_(c0);
            tc1 = tanhf_(c1);
        }
        float tX0 = __shfl_xor_sync(0xFFFFFFFFu, tc0, 1);
        float tX1 = __shfl_xor_sync(0xFFFFFFFFu, tc1, 1);
        if (odd) {
            float h0n = b0a * tX0;                   // h = o*tanh(c)
            float h1n = b1a * tX1;
            sh_h[0][(ts + 1) & 1][r] = h0n;
            sh_h[1][(ts + 1) & 1][r] = h1n;
            ho0 = h0n; ho1 = h1n;
        }

        xg0 = nx0; xg1 = nx1;
        pf0 += inc; pf1 += inc;
        __syncthreads();                             // h visible next step
    }

    if (odd) {
        out[(size_t)(b0 + 0) * H_ + r] = ho0;
        out[(size_t)(b0 + 1) * H_ + r] = ho1;
    }
}

// ---------------------------------------------------------------------------
extern "C" void kernel_launch(void* const* d_in, const int* in_sizes, int n_in,
                              void* d_out, int out_size)
{
    const float* X    = (const float*)d_in[0];   // [128,4096,64]
    const float* W_ih = (const float*)d_in[1];   // [512,64]
    const float* W_hh = (const float*)d_in[2];   // [512,128]
    const float* b_ih = (const float*)d_in[3];   // [512]
    const float* b_hh = (const float*)d_in[4];   // [512]
    float* out = (float*)d_out;                  // [128,128]

    size_t smem1 = (size_t)(512 * 65 + 64 * 64) * sizeof(float);  // ~146 KB
    cudaFuncSetAttribute(xg_kernel,
                         cudaFuncAttributeMaxDynamicSharedMemorySize, (int)smem1);

    size_t smem2 = 12 * 256 * sizeof(uint4);     // 48 KB dynamic (bf16 W)
    cudaFuncSetAttribute(lstm_kernel,
                         cudaFuncAttributeMaxDynamicSharedMemorySize, (int)smem2);

    dim3 g1(T_ / 64, B_);
    xg_kernel<<<g1, 256, smem1>>>(X, W_ih, b_ih, b_hh);
    lstm_kernel<<<B_ / 2, 256, smem2>>>(W_hh, out);
}

// round 17
// speedup vs baseline: 1.5971x; 1.5971x over previous
#include <cuda_runtime.h>
#include <cuda_bf16.h>
#include <cstdint>

#define B_ 128
#define T_ 4096
#define F_ 64
#define H_ 128
#define G_ 512   /* 4*H */

// Scratch: precomputed input gates xg[b][t][512] (PLAIN row order, as R1).
__device__ float g_xg[268435456ull];   // 1 GiB

// ---------------- f32x2 helpers (packed fp32: 2x FFMA throughput) ----------
__device__ __forceinline__ unsigned long long packf2(float x, float y) {
    unsigned long long r;
    asm("mov.b64 %0, {%1, %2};" : "=l"(r) : "f"(x), "f"(y));
    return r;
}
__device__ __forceinline__ float2 unpackf2(unsigned long long v) {
    float2 r;
    asm("mov.b64 {%0, %1}, %2;" : "=f"(r.x), "=f"(r.y) : "l"(v));
    return r;
}
__device__ __forceinline__ unsigned long long ffma2(unsigned long long a,
                                                    unsigned long long b,
                                                    unsigned long long c) {
    unsigned long long d;
    asm("fma.rn.f32x2 %0, %1, %2, %3;" : "=l"(d) : "l"(a), "l"(b), "l"(c));
    return d;
}
// bf16x2 (u32) -> f32x2 (u64): ALU-pipe unpack.
__device__ __forceinline__ unsigned long long bf2tof2(unsigned int u) {
    unsigned int lo = u << 16;
    unsigned int hi = u & 0xFFFF0000u;
    unsigned long long r;
    asm("mov.b64 %0, {%1, %2};" : "=l"(r) : "r"(lo), "r"(hi));
    return r;
}

__device__ __forceinline__ float sigmoidf_(float x) {
    return __fdividef(1.0f, 1.0f + __expf(-x));
}
__device__ __forceinline__ float tanhf_(float x) {
    float ax = fabsf(x);
    float e  = __expf(-2.0f * ax);           // e in (0,1], never overflows
    float t  = __fdividef(1.0f - e, 1.0f + e);
    return copysignf(t, x);
}

// ---------------------------------------------------------------------------
// Kernel 1: xg[b][t][j] = sum_f X[b][t][f]*W_ih[j][f] + b_ih[j] + b_hh[j]
// EXACT R1 structure; only change: sX read as ulonglong2 (no packs).
// ---------------------------------------------------------------------------
__global__ __launch_bounds__(256) void xg_kernel(
    const float* __restrict__ X,
    const float* __restrict__ W_ih,
    const float* __restrict__ b_ih,
    const float* __restrict__ b_hh)
{
    extern __shared__ float smem[];
    float* sW = smem;                 // 512 x 65 (pad 1 -> conflict-free)
    float* sX = smem + 512 * 65;      // 64 x 64

    const int t  = threadIdx.x;
    const int b  = blockIdx.y;
    const int t0 = blockIdx.x * 64;

    for (int idx = t; idx < 512 * 64; idx += 256) {
        int j = idx >> 6, k = idx & 63;
        sW[j * 65 + k] = W_ih[idx];
    }
    const float* Xb = X + ((size_t)b * T_ + t0) * F_;
    for (int idx = t; idx < 64 * 64; idx += 256) sX[idx] = Xb[idx];
    __syncthreads();

    const int r0 = t, r1 = t + 256;

    unsigned long long wpA[32], wpB[32];
#pragma unroll
    for (int p = 0; p < 32; ++p) {
        wpA[p] = packf2(sW[r0 * 65 + 2 * p], sW[r0 * 65 + 2 * p + 1]);
        wpB[p] = packf2(sW[r1 * 65 + 2 * p], sW[r1 * 65 + 2 * p + 1]);
    }
    const float biasA = __ldg(b_ih + r0) + __ldg(b_hh + r0);
    const float biasB = __ldg(b_ih + r1) + __ldg(b_hh + r1);

    float* outb = g_xg + ((size_t)b * T_ + t0) * G_;

    for (int tt = 0; tt < 64; ++tt) {
        const ulonglong2* x2 = (const ulonglong2*)(sX + tt * 64);
        unsigned long long aA0 = 0, aA1 = 0, aB0 = 0, aB1 = 0;
#pragma unroll
        for (int q = 0; q < 16; ++q) {
            ulonglong2 hq = x2[q];            // LDS.128 -> direct f32x2 pair
            aA0 = ffma2(wpA[2 * q],     hq.x, aA0);
            aA1 = ffma2(wpA[2 * q + 1], hq.y, aA1);
            aB0 = ffma2(wpB[2 * q],     hq.x, aB0);
            aB1 = ffma2(wpB[2 * q + 1], hq.y, aB1);
        }
        float2 u0 = unpackf2(aA0), u1 = unpackf2(aA1);
        float2 v0 = unpackf2(aB0), v1 = unpackf2(aB1);
        outb[(size_t)tt * G_ + r0] = (u0.x + u0.y) + (u1.x + u1.y) + biasA;
        outb[(size_t)tt * G_ + r1] = (v0.x + v0.y) + (v1.x + v1.y) + biasB;
    }
}

// ---------------------------------------------------------------------------
// Kernel 2: persistent recurrent LSTM — EXACT R1 champion structure
// (2 barriers, sh_ig handoff, 96 fp32 resident + 32 bf16 streamed, plain xg
// layout, explicit prefetch). ONLY change vs R1: h read as ulonglong2 so
// LDS.128 results feed ffma2 directly (removes 64 mov.b64 packs/thread/step).
// Thread t owns rows (t, t+256): t<128 -> (i_t, g_t); t>=128 -> (f_j, o_j).
// ---------------------------------------------------------------------------
__global__ __launch_bounds__(256, 1) void lstm_kernel(
    const float* __restrict__ W_hh,
    float* __restrict__ out)
{
    __shared__ alignas(16) float sh_h[128];
    __shared__ float sh_ig[128];
    __shared__ uint4 sws[8][256];   // streamed bf16 weight pairs, [vec][thread]

    const int t = threadIdx.x;
    const int b = blockIdx.x;
    const int r0 = t, r1 = t + 256;

    const float* WA = W_hh + (size_t)r0 * H_;
    const float* WB = W_hh + (size_t)r1 * H_;

    // Register-resident weights, k = 0..95 (48 f32x2 pairs per row)
    unsigned long long wpA[48], wpB[48];
#pragma unroll
    for (int q = 0; q < 24; ++q) {
        float4 a = __ldg((const float4*)(WA + 4 * q));
        wpA[2 * q]     = packf2(a.x, a.y);
        wpA[2 * q + 1] = packf2(a.z, a.w);
        float4 c4 = __ldg((const float4*)(WB + 4 * q));
        wpB[2 * q]     = packf2(c4.x, c4.y);
        wpB[2 * q + 1] = packf2(c4.z, c4.w);
    }
    // Streamed weights, k = 96..127, packed bf16x2 into shared
    {
        unsigned int uA[16], uB[16];
#pragma unroll
        for (int p = 0; p < 16; ++p) {
            float a0 = __ldg(WA + 96 + 2 * p), a1 = __ldg(WA + 97 + 2 * p);
            float c0 = __ldg(WB + 96 + 2 * p), c1 = __ldg(WB + 97 + 2 * p);
            unsigned short sa0 = __bfloat16_as_ushort(__float2bfloat16(a0));
            unsigned short sa1 = __bfloat16_as_ushort(__float2bfloat16(a1));
            unsigned short sb0 = __bfloat16_as_ushort(__float2bfloat16(c0));
            unsigned short sb1 = __bfloat16_as_ushort(__float2bfloat16(c1));
            uA[p] = ((unsigned)sa1 << 16) | (unsigned)sa0;
            uB[p] = ((unsigned)sb1 << 16) | (unsigned)sb0;
        }
#pragma unroll
        for (int i = 0; i < 4; ++i) {
            sws[i][t]     = make_uint4(uA[4*i], uA[4*i+1], uA[4*i+2], uA[4*i+3]);
            sws[4 + i][t] = make_uint4(uB[4*i], uB[4*i+1], uB[4*i+2], uB[4*i+3]);
        }
    }
    if (t < 128) sh_h[t] = 0.0f;
    __syncthreads();

    const float* xb = g_xg + (size_t)b * T_ * G_;
    const float* pA = xb + r0;
    const float* pB = xb + r1;
    float xgA = __ldg(pA);
    float xgB = __ldg(pB);

    float c = 0.0f;
    float h_out = 0.0f;
    const ulonglong2* h2p = (const ulonglong2*)sh_h;

    for (int ts = 0; ts < T_; ++ts) {
        // software prefetch of next step's xg (covers DRAM latency)
        const int inc = (ts < T_ - 1) ? G_ : 0;
        float nxA = __ldg(pA + inc);
        float nxB = __ldg(pB + inc);

        unsigned long long aA0 = 0, aA1 = 0, aB0 = 0, aB1 = 0;
#pragma unroll
        for (int q = 0; q < 24; ++q) {        // k = 0..95, register weights
            ulonglong2 hq = h2p[q];            // broadcast LDS.128, no packs
            aA0 = ffma2(wpA[2 * q],     hq.x, aA0);
            aA1 = ffma2(wpA[2 * q + 1], hq.y, aA1);
            aB0 = ffma2(wpB[2 * q],     hq.x, aB0);
            aB1 = ffma2(wpB[2 * q + 1], hq.y, aB1);
        }
#pragma unroll
        for (int i = 0; i < 4; ++i) {         // k = 96..127, streamed bf16
            uint4 ua = sws[i][t];
            uint4 ub = sws[4 + i][t];
            ulonglong2 h0 = h2p[24 + 2 * i];   // h[96+8i .. 99+8i]
            ulonglong2 h1 = h2p[25 + 2 * i];   // h[100+8i .. 103+8i]
            aA0 = ffma2(bf2tof2(ua.x), h0.x, aA0);
            aA1 = ffma2(bf2tof2(ua.y), h0.y, aA1);
            aA0 = ffma2(bf2tof2(ua.z), h1.x, aA0);
            aA1 = ffma2(bf2tof2(ua.w), h1.y, aA1);
            aB0 = ffma2(bf2tof2(ub.x), h0.x, aB0);
            aB1 = ffma2(bf2tof2(ub.y), h0.y, aB1);
            aB0 = ffma2(bf2tof2(ub.z), h1.x, aB0);
            aB1 = ffma2(bf2tof2(ub.w), h1.y, aB1);
        }
        float2 u0 = unpackf2(aA0), u1 = unpackf2(aA1);
        float2 w0 = unpackf2(aB0), w1 = unpackf2(aB1);
        float gA = (u0.x + u0.y) + (u1.x + u1.y) + xgA;
        float gB = (w0.x + w0.y) + (w1.x + w1.y) + xgB;

        float fg = 0.0f, og = 0.0f;
        if (t < 128) {
            sh_ig[t] = sigmoidf_(gA) * tanhf_(gB);   // i * g
        } else {
            fg = sigmoidf_(gA);                       // f
            og = sigmoidf_(gB);                       // o
        }
        __syncthreads();                              // ig visible
        if (t >= 128) {
            c = fg * c + sh_ig[t - 128];
            float h = og * tanhf_(c);
            sh_h[t - 128] = h;
            h_out = h;
        }
        __syncthreads();                              // h visible for next step

        pA += inc; pB += inc;
        xgA = nxA; xgB = nxB;
    }

    if (t >= 128) out[(size_t)b * H_ + (t - 128)] = h_out;
}

// ---------------------------------------------------------------------------
extern "C" void kernel_launch(void* const* d_in, const int* in_sizes, int n_in,
                              void* d_out, int out_size)
{
    const float* X    = (const float*)d_in[0];   // [128,4096,64]
    const float* W_ih = (const float*)d_in[1];   // [512,64]
    const float* W_hh = (const float*)d_in[2];   // [512,128]
    const float* b_ih = (const float*)d_in[3];   // [512]
    const float* b_hh = (const float*)d_in[4];   // [512]
    float* out = (float*)d_out;                  // [128,128]

    size_t smem1 = (size_t)(512 * 65 + 64 * 64) * sizeof(float);  // ~146 KB
    cudaFuncSetAttribute(xg_kernel,
                         cudaFuncAttributeMaxDynamicSharedMemorySize, (int)smem1);

    dim3 g1(T_ / 64, B_);
    xg_kernel<<<g1, 256, smem1>>>(X, W_ih, b_ih, b_hh);
    lstm_kernel<<<B_, 256>>>(W_hh, out);
}